// round 6
// baseline (speedup 1.0000x reference)
#include <cuda_runtime.h>
#include <math.h>

#define VOCAB   50257
#define EMBED   128
#define HIDDEN  128
#define NCLASS  4
#define BB      256
#define TT      512
#define NTOK    (BB * TT)          // 131072

// x_proj scratch [t][b][h] : 64MB device global (no runtime alloc)
__device__ float g_xp[TT * BB * HIDDEN];

// ---------------------------------------------------------------- helpers
__device__ __forceinline__ unsigned smem_u32(const void* p) {
    return (unsigned)__cvta_generic_to_shared(p);
}
__device__ __forceinline__ void cp_async16(void* dst, const void* src) {
    asm volatile("cp.async.cg.shared.global [%0], [%1], 16;"
                 :: "r"(smem_u32(dst)), "l"(src));
}
__device__ __forceinline__ void cp_commit() {
    asm volatile("cp.async.commit_group;");
}
__device__ __forceinline__ void cp_wait1() {
    asm volatile("cp.async.wait_group 1;");
}
__device__ __forceinline__ void cp_wait0() {
    asm volatile("cp.async.wait_group 0;");
}
// packed dual fp32 FMA (sm_103a f32x2 pipe)
__device__ __forceinline__ unsigned long long
fma2(unsigned long long a, unsigned long long b, unsigned long long c) {
    unsigned long long d;
    asm("fma.rn.f32x2 %0, %1, %2, %3;" : "=l"(d) : "l"(a), "l"(b), "l"(c));
    return d;
}
__device__ __forceinline__ float2 unpack2(unsigned long long v) {
    float2 r;
    asm("mov.b64 {%0, %1}, %2;" : "=f"(r.x), "=f"(r.y) : "l"(v));
    return r;
}
__device__ __forceinline__ float fast_tanh(float x) {
    x = fminf(fmaxf(x, -15.0f), 15.0f);
    float e = __expf(2.0f * x);
    return 1.0f - __fdividef(2.0f, e + 1.0f);
}

// ---------------------------------------------------------------------------
// Thread decomposition (both GEMM kernels):
//   lane = q*8 + oid  (q = K-quarter 0..3, oid = out-pair 0..7)
//   warp covers 16 consecutive outputs (obase = (wid&7)*16), thread owns
//   outs o0 = obase + oid*2, o1 = o0+1, K range [q*32, q*32+32).
// Activations live in shared in INTERLEAVED layout per 128-float row:
//   float k -> offset (k&31)>>2 * 16 + (k>>5)*4 + (k&3)
// so at dot-step j all 32 lanes read one contiguous 64B span = 1 wavefront.
// K-quarter partials reduced with shfl_xor(8) + shfl_xor(16).
// ---------------------------------------------------------------------------

// interleaved float offset for scalar k within a 128-float row
__device__ __forceinline__ int ilv_off(int k) {
    return ((k & 31) >> 2) * 16 + (k >> 5) * 4 + (k & 3);
}

// dot over this thread's K-quarter for 2 outputs.
// srcq = (ulonglong2*)(row_base) + q ; step stride 4 ulonglong2 (64B).
// wA,wB: 16 u64 each (weights for o0,o1 over the quarter, contiguous k).
__device__ __forceinline__ float2 dot32x2(
    const ulonglong2* __restrict__ srcq,
    const unsigned long long* __restrict__ wA,
    const unsigned long long* __restrict__ wB)
{
    unsigned long long a0 = 0, a1 = 0, b0 = 0, b1 = 0;
    #pragma unroll
    for (int j = 0; j < 8; ++j) {
        ulonglong2 v = srcq[j * 4];
        a0 = fma2(wA[2 * j],     v.x, a0);
        a1 = fma2(wA[2 * j + 1], v.y, a1);
        b0 = fma2(wB[2 * j],     v.x, b0);
        b1 = fma2(wB[2 * j + 1], v.y, b1);
    }
    float2 ua0 = unpack2(a0), ua1 = unpack2(a1);
    float2 ub0 = unpack2(b0), ub1 = unpack2(b1);
    float d0 = (ua0.x + ua0.y) + (ua1.x + ua1.y);
    float d1 = (ub0.x + ub0.y) + (ub1.x + ub1.y);
    d0 += __shfl_xor_sync(0xffffffffu, d0, 8);
    d0 += __shfl_xor_sync(0xffffffffu, d0, 16);
    d1 += __shfl_xor_sync(0xffffffffu, d1, 8);
    d1 += __shfl_xor_sync(0xffffffffu, d1, 16);
    return make_float2(d0, d1);
}

// load this thread's weight slice (2 outs x 32 k) from a staged 32-row pass
__device__ __forceinline__ void load_wslice(
    const float* __restrict__ s_stg, int o0, int q,
    unsigned long long* __restrict__ wA, unsigned long long* __restrict__ wB)
{
    const unsigned long long* rA =
        (const unsigned long long*)(s_stg + (o0 & 31) * 128 + q * 32);
    const unsigned long long* rB =
        (const unsigned long long*)(s_stg + ((o0 & 31) + 1) * 128 + q * 32);
    #pragma unroll
    for (int k = 0; k < 16; ++k) { wA[k] = rA[k]; wB[k] = rB[k]; }
}

// ---------------------------------------------------------------------------
// Kernel 1: x_proj = emb[x] @ W_ih^T + (b_ih + b_hh)
// 148 CTAs x 512 threads (16 warps). Warps 0-7 process token slots 0-7,
// warps 8-15 slots 8-15 (each warp-group covers all 128 outputs).
// Embeddings staged 16 tokens/chunk via cp.async into interleaved layout.
// ---------------------------------------------------------------------------
#define XP_GRID  148
#define XP_TPC   886            // tokens per CTA (148*886 >= 131072)
#define XP_CH    16
#define XP_NC    ((XP_TPC + XP_CH - 1) / XP_CH)   // 56

// shared floats: ids[896] | act[2][16*128]
#define XPS_IDS   0
#define XPS_ACT   896
#define XPS_TOT   (896 + 4096)

__global__ void __launch_bounds__(512, 1) xproj_kernel(
    const int* __restrict__ x, const float* __restrict__ emb,
    const float* __restrict__ W_ih, const float* __restrict__ b_ih,
    const float* __restrict__ b_hh)
{
    extern __shared__ float sh[];
    int*   s_ids = (int*)(sh + XPS_IDS);
    float* s_act = sh + XPS_ACT;

    const int tid  = threadIdx.x;
    const int lane = tid & 31;
    const int wid  = tid >> 5;
    const int oid  = lane & 7;
    const int q    = lane >> 3;
    const int o0   = ((wid & 7) << 4) + oid * 2;
    const int sub  = wid >> 3;           // token-slot group
    const int r0   = blockIdx.x * XP_TPC;

    // stage token ids (pad with 0 -> emb pad row is zero)
    for (int i = tid; i < 896; i += 512) {
        int r = r0 + i;
        s_ids[i] = (i < XP_TPC && r < NTOK) ? x[r] : 0;
    }

    // stage W_ih -> per-thread weight slices (4 coalesced passes via s_act)
    unsigned long long wA[16], wB[16];
    for (int p = 0; p < 4; ++p) {
        for (int i = tid; i < 4096; i += 512)
            s_act[i] = W_ih[p * 4096 + i];
        __syncthreads();
        if ((o0 >> 5) == p) load_wslice(s_act, o0, q, wA, wB);
        __syncthreads();
    }
    const float bias0 = b_ih[o0] + b_hh[o0];
    const float bias1 = b_ih[o0 + 1] + b_hh[o0 + 1];

    // staging lambda-ish: thread (slot = tid>>5, k4 = tid&31) copies 16B into
    // the interleaved position of that token row.
    const int st_slot = tid >> 5;
    const int st_k4   = tid & 31;
    const int st_dst  = st_slot * 128 + (st_k4 & 7) * 16 + (st_k4 >> 3) * 4;
    const int st_src  = st_k4 * 4;

    // prologue: stage chunk 0
    {
        int id = s_ids[st_slot];
        cp_async16(s_act + st_dst, emb + (size_t)id * EMBED + st_src);
        cp_commit();
    }

    for (int c = 0; c < XP_NC; ++c) {
        if (c + 1 < XP_NC) {
            float* dst = s_act + ((c + 1) & 1) * 2048;
            int id = s_ids[(c + 1) * XP_CH + st_slot];
            cp_async16(dst + st_dst, emb + (size_t)id * EMBED + st_src);
            cp_commit();
            cp_wait1();
        } else {
            cp_wait0();
        }
        __syncthreads();   // chunk c data visible

        const float* buf = s_act + (c & 1) * 2048;
        #pragma unroll 2
        for (int j = 0; j < 8; ++j) {
            int slot = sub * 8 + j;
            const ulonglong2* srcq =
                (const ulonglong2*)(buf + slot * 128) + q;
            float2 d = dot32x2(srcq, wA, wB);
            int i_tok = c * XP_CH + slot;
            int r = r0 + i_tok;
            if (q == 0 && i_tok < XP_TPC && r < NTOK) {
                int b = r >> 9, t = r & (TT - 1);
                float2 v = make_float2(d.x + bias0, d.y + bias1);
                *(float2*)(g_xp + ((size_t)t * BB + b) * HIDDEN + o0) = v;
            }
        }
        __syncthreads();   // done reading buf c before re-stage
    }
}

// ---------------------------------------------------------------------------
// Kernel 2: recurrence. 128 CTAs x 512 threads (1 CTA/SM). row = wid>>3.
// h kept in shared in the SAME interleaved layout, double-buffered.
// One __syncthreads per step; q==0 lanes do tanh + publish h (float2 STS).
// ---------------------------------------------------------------------------
// shared floats: h[2 bufs][2 rows][128] | stage[4096]
#define RNS_H     0
#define RNS_STG   512
#define RNS_TOT   (512 + 4096)

__global__ void __launch_bounds__(512, 1) rnn_kernel(
    const float* __restrict__ h0, const float* __restrict__ W_hh,
    float* __restrict__ out_hidden)
{
    extern __shared__ float sh[];
    float* s_h   = sh + RNS_H;
    float* s_stg = sh + RNS_STG;

    const int tid  = threadIdx.x;
    const int lane = tid & 31;
    const int wid  = tid >> 5;
    const int oid  = lane & 7;
    const int q    = lane >> 3;
    const int o0   = ((wid & 7) << 4) + oid * 2;
    const int row  = wid >> 3;
    const int b    = blockIdx.x * 2 + row;
    const int hoff = ilv_off(o0);        // o0 even -> o0,o0+1 contiguous

    // stage W_hh -> weight slices
    unsigned long long wA[16], wB[16];
    for (int p = 0; p < 4; ++p) {
        for (int i = tid; i < 4096; i += 512)
            s_stg[i] = W_hh[p * 4096 + i];
        __syncthreads();
        if ((o0 >> 5) == p) load_wslice(s_stg, o0, q, wA, wB);
        __syncthreads();
    }

    // init h buffer 0 (interleaved)
    if (q == 0) {
        float2 hv = *(const float2*)(h0 + (size_t)b * HIDDEN + o0);
        *(float2*)(s_h + row * 128 + hoff) = hv;
    }
    __syncthreads();

    const float* xp_me = g_xp + (size_t)b * HIDDEN + o0;
    float2 xv0 = make_float2(0.f, 0.f), xv1 = xv0;
    if (q == 0) {
        xv0 = *(const float2*)xp_me;
        xv1 = *(const float2*)(xp_me + (size_t)(BB * HIDDEN));
    }
    float2 hcur = make_float2(0.f, 0.f);

    for (int t = 0; t < TT; ++t) {
        float2 xv2 = make_float2(0.f, 0.f);
        if (q == 0 && t + 2 < TT)
            xv2 = *(const float2*)(xp_me + (size_t)(t + 2) * (BB * HIDDEN));

        const ulonglong2* srcq = (const ulonglong2*)
            (s_h + (t & 1) * 256 + row * 128) + q;
        float2 d = dot32x2(srcq, wA, wB);

        if (q == 0) {
            hcur.x = fast_tanh(d.x + xv0.x);
            hcur.y = fast_tanh(d.y + xv0.y);
            *(float2*)(s_h + ((t + 1) & 1) * 256 + row * 128 + hoff) = hcur;
            xv0 = xv1; xv1 = xv2;
        }
        __syncthreads();   // publish h[t+1]
    }

    if (q == 0)
        *(float2*)(out_hidden + (size_t)b * HIDDEN + o0) = hcur;
}

// ---------------------------------------------------------------------------
// Kernel 3: MLP head. One CTA per batch row.
// ---------------------------------------------------------------------------
__global__ void __launch_bounds__(256) head_kernel(
    const float* __restrict__ hidden, const float* __restrict__ W1,
    const float* __restrict__ b1, const float* __restrict__ W2,
    const float* __restrict__ b2, float* __restrict__ logits)
{
    __shared__ float shH[HIDDEN];
    __shared__ float shM[2 * HIDDEN];
    const int b = blockIdx.x, tid = threadIdx.x;
    if (tid < HIDDEN) shH[tid] = hidden[(size_t)b * HIDDEN + tid];
    __syncthreads();

    float acc = b1[tid];
    const float4* w4 = (const float4*)(W1 + (size_t)tid * HIDDEN);
    const float4* h4 = (const float4*)shH;
    #pragma unroll 8
    for (int k4 = 0; k4 < 32; ++k4) {
        float4 w = w4[k4];
        float4 h = h4[k4];
        acc = fmaf(w.x, h.x, acc);
        acc = fmaf(w.y, h.y, acc);
        acc = fmaf(w.z, h.z, acc);
        acc = fmaf(w.w, h.w, acc);
    }
    shM[tid] = fmaxf(acc, 0.0f);
    __syncthreads();

    if (tid < NCLASS) {
        float a = b2[tid];
        const float* w2 = W2 + (size_t)tid * (2 * HIDDEN);
        #pragma unroll 8
        for (int k = 0; k < 2 * HIDDEN; ++k)
            a = fmaf(shM[k], w2[k], a);
        logits[(size_t)b * NCLASS + tid] = a;
    }
}

// ---------------------------------------------------------------------------
extern "C" void kernel_launch(void* const* d_in, const int* in_sizes, int n_in,
                              void* d_out, int out_size)
{
    const int*   x    = (const int*)  d_in[0];
    const float* h0   = (const float*)d_in[1];
    const float* emb  = (const float*)d_in[2];
    const float* W_ih = (const float*)d_in[3];
    const float* W_hh = (const float*)d_in[4];
    const float* b_ih = (const float*)d_in[5];
    const float* b_hh = (const float*)d_in[6];
    const float* W1   = (const float*)d_in[7];
    const float* b1   = (const float*)d_in[8];
    const float* W2   = (const float*)d_in[9];
    const float* b2   = (const float*)d_in[10];

    float* out    = (float*)d_out;
    float* logits = out;                 // [256*4]
    float* hidden = out + BB * NCLASS;   // [256*128]

    const int smem1 = XPS_TOT * sizeof(float);   // ~20KB
    const int smem2 = RNS_TOT * sizeof(float);   // ~18KB

    xproj_kernel<<<XP_GRID, 512, smem1>>>(x, emb, W_ih, b_ih, b_hh);
    rnn_kernel<<<BB / 2, 512, smem2>>>(h0, W_hh, hidden);
    head_kernel<<<BB, 256>>>(hidden, W1, b1, W2, b2, logits);
}

// round 8
// speedup vs baseline: 1.2159x; 1.2159x over previous
#include <cuda_runtime.h>
#include <math.h>

#define VOCAB   50257
#define EMBED   128
#define HIDDEN  128
#define NCLASS  4
#define BB      256
#define TT      512
#define NTOK    (BB * TT)          // 131072

// x_proj scratch [t][b][h] : 64MB device global (no runtime alloc)
__device__ float g_xp[TT * BB * HIDDEN];

// ---------------------------------------------------------------- helpers
__device__ __forceinline__ unsigned smem_u32(const void* p) {
    return (unsigned)__cvta_generic_to_shared(p);
}
__device__ __forceinline__ void cp_async16(void* dst, const void* src) {
    asm volatile("cp.async.cg.shared.global [%0], [%1], 16;"
                 :: "r"(smem_u32(dst)), "l"(src));
}
__device__ __forceinline__ void cp_commit() {
    asm volatile("cp.async.commit_group;");
}
__device__ __forceinline__ void cp_wait1() {
    asm volatile("cp.async.wait_group 1;");
}
__device__ __forceinline__ void cp_wait0() {
    asm volatile("cp.async.wait_group 0;");
}
// packed dual fp32 FMA (sm_103a f32x2 pipe)
__device__ __forceinline__ unsigned long long
fma2(unsigned long long a, unsigned long long b, unsigned long long c) {
    unsigned long long d;
    asm("fma.rn.f32x2 %0, %1, %2, %3;" : "=l"(d) : "l"(a), "l"(b), "l"(c));
    return d;
}
__device__ __forceinline__ float2 unpack2(unsigned long long v) {
    float2 r;
    asm("mov.b64 {%0, %1}, %2;" : "=f"(r.x), "=f"(r.y) : "l"(v));
    return r;
}
__device__ __forceinline__ float fast_tanh(float x) {
    x = fminf(fmaxf(x, -15.0f), 15.0f);
    float e = __expf(2.0f * x);
    return 1.0f - __fdividef(2.0f, e + 1.0f);
}

// ---------------------------------------------------------------------------
// Kernel 1 (unchanged from round 6 — best measured: 152us):
// x_proj = emb[x] @ W_ih^T + (b_ih + b_hh)
// lane = q*8 + oid; thread owns outs o0,o1 over K-quarter q. Activations in
// interleaved shared layout so each LDS.128 is a single 64B wavefront.
// ---------------------------------------------------------------------------
#define XP_GRID  148
#define XP_TPC   886            // tokens per CTA (148*886 >= 131072)
#define XP_CH    16
#define XP_NC    ((XP_TPC + XP_CH - 1) / XP_CH)   // 56

// shared floats: ids[896] | act[2][16*128]
#define XPS_IDS   0
#define XPS_ACT   896
#define XPS_TOT   (896 + 4096)

__device__ __forceinline__ float2 dot32x2(
    const ulonglong2* __restrict__ srcq,
    const unsigned long long* __restrict__ wA,
    const unsigned long long* __restrict__ wB)
{
    unsigned long long a0 = 0, a1 = 0, b0 = 0, b1 = 0;
    #pragma unroll
    for (int j = 0; j < 8; ++j) {
        ulonglong2 v = srcq[j * 4];
        a0 = fma2(wA[2 * j],     v.x, a0);
        a1 = fma2(wA[2 * j + 1], v.y, a1);
        b0 = fma2(wB[2 * j],     v.x, b0);
        b1 = fma2(wB[2 * j + 1], v.y, b1);
    }
    float2 ua0 = unpack2(a0), ua1 = unpack2(a1);
    float2 ub0 = unpack2(b0), ub1 = unpack2(b1);
    float d0 = (ua0.x + ua0.y) + (ua1.x + ua1.y);
    float d1 = (ub0.x + ub0.y) + (ub1.x + ub1.y);
    d0 += __shfl_xor_sync(0xffffffffu, d0, 8);
    d0 += __shfl_xor_sync(0xffffffffu, d0, 16);
    d1 += __shfl_xor_sync(0xffffffffu, d1, 8);
    d1 += __shfl_xor_sync(0xffffffffu, d1, 16);
    return make_float2(d0, d1);
}

__device__ __forceinline__ void load_wslice(
    const float* __restrict__ s_stg, int o0, int q,
    unsigned long long* __restrict__ wA, unsigned long long* __restrict__ wB)
{
    const unsigned long long* rA =
        (const unsigned long long*)(s_stg + (o0 & 31) * 128 + q * 32);
    const unsigned long long* rB =
        (const unsigned long long*)(s_stg + ((o0 & 31) + 1) * 128 + q * 32);
    #pragma unroll
    for (int k = 0; k < 16; ++k) { wA[k] = rA[k]; wB[k] = rB[k]; }
}

__global__ void __launch_bounds__(512, 1) xproj_kernel(
    const int* __restrict__ x, const float* __restrict__ emb,
    const float* __restrict__ W_ih, const float* __restrict__ b_ih,
    const float* __restrict__ b_hh)
{
    extern __shared__ float sh[];
    int*   s_ids = (int*)(sh + XPS_IDS);
    float* s_act = sh + XPS_ACT;

    const int tid  = threadIdx.x;
    const int lane = tid & 31;
    const int wid  = tid >> 5;
    const int oid  = lane & 7;
    const int q    = lane >> 3;
    const int o0   = ((wid & 7) << 4) + oid * 2;
    const int sub  = wid >> 3;           // token-slot group
    const int r0   = blockIdx.x * XP_TPC;

    for (int i = tid; i < 896; i += 512) {
        int r = r0 + i;
        s_ids[i] = (i < XP_TPC && r < NTOK) ? x[r] : 0;
    }

    unsigned long long wA[16], wB[16];
    for (int p = 0; p < 4; ++p) {
        for (int i = tid; i < 4096; i += 512)
            s_act[i] = W_ih[p * 4096 + i];
        __syncthreads();
        if ((o0 >> 5) == p) load_wslice(s_act, o0, q, wA, wB);
        __syncthreads();
    }
    const float bias0 = b_ih[o0] + b_hh[o0];
    const float bias1 = b_ih[o0 + 1] + b_hh[o0 + 1];

    const int st_slot = tid >> 5;
    const int st_k4   = tid & 31;
    const int st_dst  = st_slot * 128 + (st_k4 & 7) * 16 + (st_k4 >> 3) * 4;
    const int st_src  = st_k4 * 4;

    {
        int id = s_ids[st_slot];
        cp_async16(s_act + st_dst, emb + (size_t)id * EMBED + st_src);
        cp_commit();
    }

    for (int c = 0; c < XP_NC; ++c) {
        if (c + 1 < XP_NC) {
            float* dst = s_act + ((c + 1) & 1) * 2048;
            int id = s_ids[(c + 1) * XP_CH + st_slot];
            cp_async16(dst + st_dst, emb + (size_t)id * EMBED + st_src);
            cp_commit();
            cp_wait1();
        } else {
            cp_wait0();
        }
        __syncthreads();

        const float* buf = s_act + (c & 1) * 2048;
        #pragma unroll 2
        for (int j = 0; j < 8; ++j) {
            int slot = sub * 8 + j;
            const ulonglong2* srcq =
                (const ulonglong2*)(buf + slot * 128) + q;
            float2 d = dot32x2(srcq, wA, wB);
            int i_tok = c * XP_CH + slot;
            int r = r0 + i_tok;
            if (q == 0 && i_tok < XP_TPC && r < NTOK) {
                int b = r >> 9, t = r & (TT - 1);
                float2 v = make_float2(d.x + bias0, d.y + bias1);
                *(float2*)(g_xp + ((size_t)t * BB + b) * HIDDEN + o0) = v;
            }
        }
        __syncthreads();
    }
}

// ---------------------------------------------------------------------------
// Kernel 2: recurrence. 256 CTAs x 128 threads, ONE batch row per CTA,
// 2 CTAs resident per SM (independent barriers -> mutual latency hiding).
// Thread owns one output with the full 128-float W_hh row in registers.
// h double-buffered in shared; broadcast LDS.128 (1 wavefront); no reduce;
// one 4-warp __syncthreads per step. xp prefetched 2 steps ahead.
// FIX vs round 7: dot loop covers all 32 ulonglong2 (128 floats), w2[0..63].
// ---------------------------------------------------------------------------
// shared floats: h[2][128] | stage[4096]
#define RNS_H     0
#define RNS_STG   256
#define RNS_TOT   (256 + 4096)

__global__ void __launch_bounds__(128, 2) rnn_kernel(
    const float* __restrict__ h0, const float* __restrict__ W_hh,
    float* __restrict__ out_hidden)
{
    extern __shared__ float sh[];
    float* s_h   = sh + RNS_H;
    float* s_stg = sh + RNS_STG;

    const int out = threadIdx.x;          // 0..127
    const int b   = blockIdx.x;

    // stage W_hh rows -> registers (4 coalesced passes through shared)
    unsigned long long w2[64];
    for (int p = 0; p < 4; ++p) {
        for (int i = out; i < 4096; i += 128)
            s_stg[i] = W_hh[p * 4096 + i];
        __syncthreads();
        if ((out >> 5) == p) {
            const unsigned long long* row =
                (const unsigned long long*)(s_stg + (out & 31) * 128);
            #pragma unroll
            for (int k = 0; k < 64; ++k) w2[k] = row[k];
        }
        __syncthreads();
    }

    s_h[out] = h0[(size_t)b * HIDDEN + out];
    __syncthreads();

    const float* xp_me = g_xp + (size_t)b * HIDDEN + out;
    float xv0 = __ldg(xp_me);
    float xv1 = __ldg(xp_me + (size_t)(BB * HIDDEN));
    float h = 0.0f;

    for (int t = 0; t < TT; ++t) {
        float xv2 = (t + 2 < TT)
            ? __ldg(xp_me + (size_t)(t + 2) * (BB * HIDDEN)) : 0.0f;

        const ulonglong2* h4 = (const ulonglong2*)(s_h + (t & 1) * 128);
        unsigned long long a0 = 0, a1 = 0, a2 = 0, a3 = 0;
        #pragma unroll
        for (int k = 0; k < 32; ++k) {      // 32 x 16B = all 128 floats
            ulonglong2 v = h4[k];           // broadcast: 1 wavefront
            if (k & 1) {
                a2 = fma2(w2[2 * k],     v.x, a2);
                a3 = fma2(w2[2 * k + 1], v.y, a3);
            } else {
                a0 = fma2(w2[2 * k],     v.x, a0);
                a1 = fma2(w2[2 * k + 1], v.y, a1);
            }
        }
        float2 u0 = unpack2(a0), u1 = unpack2(a1);
        float2 u2 = unpack2(a2), u3 = unpack2(a3);
        float d = ((u0.x + u0.y) + (u1.x + u1.y)) +
                  ((u2.x + u2.y) + (u3.x + u3.y));

        h = fast_tanh(d + xv0);
        s_h[((t + 1) & 1) * 128 + out] = h;
        xv0 = xv1; xv1 = xv2;
        __syncthreads();                    // publish h[t+1] (4 warps only)
    }

    out_hidden[(size_t)b * HIDDEN + out] = h;
}

// ---------------------------------------------------------------------------
// Kernel 3: MLP head. One CTA per batch row.
// ---------------------------------------------------------------------------
__global__ void __launch_bounds__(256) head_kernel(
    const float* __restrict__ hidden, const float* __restrict__ W1,
    const float* __restrict__ b1, const float* __restrict__ W2,
    const float* __restrict__ b2, float* __restrict__ logits)
{
    __shared__ float shH[HIDDEN];
    __shared__ float shM[2 * HIDDEN];
    const int b = blockIdx.x, tid = threadIdx.x;
    if (tid < HIDDEN) shH[tid] = hidden[(size_t)b * HIDDEN + tid];
    __syncthreads();

    float acc = b1[tid];
    const float4* w4 = (const float4*)(W1 + (size_t)tid * HIDDEN);
    const float4* h4 = (const float4*)shH;
    #pragma unroll 8
    for (int k4 = 0; k4 < 32; ++k4) {
        float4 w = w4[k4];
        float4 h = h4[k4];
        acc = fmaf(w.x, h.x, acc);
        acc = fmaf(w.y, h.y, acc);
        acc = fmaf(w.z, h.z, acc);
        acc = fmaf(w.w, h.w, acc);
    }
    shM[tid] = fmaxf(acc, 0.0f);
    __syncthreads();

    if (tid < NCLASS) {
        float a = b2[tid];
        const float* w2 = W2 + (size_t)tid * (2 * HIDDEN);
        #pragma unroll 8
        for (int k = 0; k < 2 * HIDDEN; ++k)
            a = fmaf(shM[k], w2[k], a);
        logits[(size_t)b * NCLASS + tid] = a;
    }
}

// ---------------------------------------------------------------------------
extern "C" void kernel_launch(void* const* d_in, const int* in_sizes, int n_in,
                              void* d_out, int out_size)
{
    const int*   x    = (const int*)  d_in[0];
    const float* h0   = (const float*)d_in[1];
    const float* emb  = (const float*)d_in[2];
    const float* W_ih = (const float*)d_in[3];
    const float* W_hh = (const float*)d_in[4];
    const float* b_ih = (const float*)d_in[5];
    const float* b_hh = (const float*)d_in[6];
    const float* W1   = (const float*)d_in[7];
    const float* b1   = (const float*)d_in[8];
    const float* W2   = (const float*)d_in[9];
    const float* b2   = (const float*)d_in[10];

    float* out    = (float*)d_out;
    float* logits = out;                 // [256*4]
    float* hidden = out + BB * NCLASS;   // [256*128]

    const int smem1 = XPS_TOT * sizeof(float);   // ~20KB
    const int smem2 = RNS_TOT * sizeof(float);   // ~17KB

    xproj_kernel<<<XP_GRID, 512, smem1>>>(x, emb, W_ih, b_ih, b_hh);
    rnn_kernel<<<BB, 128, smem2>>>(h0, W_hh, hidden);
    head_kernel<<<BB, 256>>>(hidden, W1, b1, W2, b2, logits);
}